// round 10
// baseline (speedup 1.0000x reference)
#include <cuda_runtime.h>
#include <cstdint>

#define B_   64
#define L_   512
#define E_   512
#define HL_  1024
#define HS_  256
#define NC_  5

typedef unsigned long long ull;
#define FMA2(d, a, b, c) asm("fma.rn.f32x2 %0, %1, %2, %3;" : "=l"(d) : "l"(a), "l"(b), "l"(c))
union F2U { ull u; float2 f; };

__device__ float g_gl[(size_t)L_ * 4 * HL_ * B_];
__device__ float g_gs[(size_t)L_ * 4 * HS_ * B_];
__device__ float g_r [L_ * B_ * 2];
__device__ float g_h  [2 * HL_ * B_];
__device__ float g_hsm[2 * HS_ * B_];
__device__ float g_c  [HL_ * B_];
__device__ float g_cs [HS_ * B_];
__device__ unsigned int g_bar_arrive = 0;
__device__ unsigned int g_bar_gen    = 0;

__device__ __forceinline__ float sigf(float x) { return 1.0f / (1.0f + expf(-x)); }

__device__ __forceinline__ void grid_sync(void) {
    __syncthreads();
    if (threadIdx.x == 0) {
        unsigned int gen = *((volatile unsigned int*)&g_bar_gen);
        __threadfence();
        unsigned int a = atomicAdd(&g_bar_arrive, 1u);
        if (a == gridDim.x - 1) {
            g_bar_arrive = 0; __threadfence(); atomicAdd(&g_bar_gen, 1u);
        } else {
            while (*((volatile unsigned int*)&g_bar_gen) == gen) { __nanosleep(32); }
        }
        __threadfence();
    }
    __syncthreads();
}

__device__ __forceinline__ uint32_t tf32c(float f) {
    uint32_t u; asm("cvt.rna.tf32.f32 %0, %1;" : "=r"(u) : "f"(f)); return u;
}
__device__ __forceinline__ void mma8(float* d, uint32_t a0, uint32_t a1, uint32_t a2, uint32_t a3,
                                     uint32_t b0, uint32_t b1) {
    asm volatile("mma.sync.aligned.m16n8k8.row.col.f32.tf32.tf32.f32 "
        "{%0,%1,%2,%3}, {%4,%5,%6,%7}, {%8,%9}, {%0,%1,%2,%3};"
        : "+f"(d[0]), "+f"(d[1]), "+f"(d[2]), "+f"(d[3])
        : "r"(a0), "r"(a1), "r"(a2), "r"(a3), "r"(b0), "r"(b1));
}

__device__ void rec_gemm(const float* __restrict__ W, const float* __restrict__ hv,
                         int k0, int KD, int G, float* sg, int tid)
{
    int warp = tid >> 5, lane = tid & 31;
    int mw = warp >> 2, kw = (warp >> 1) & 1, nw = warp & 1;
    int qr = lane >> 2, q = lane & 3;
    int kb0 = kw * (KD >> 1);

    const float* ar[8];
#pragma unroll
    for (int j = 0; j < 8; ++j) {
        int m = mw * 64 + (j >> 1) * 16 + (j & 1) * 8 + qr;
        ar[j] = W + (size_t)((m >> 5) * KD + k0 + (m & 31)) * KD + kb0 + q * 4;
    }
    const float* br[4];
#pragma unroll
    for (int nt = 0; nt < 4; ++nt)
        br[nt] = hv + (size_t)(kb0 + q * 4) * 64 + nw * 32 + nt * 8 + qr;

    float acc[4][4][4];
#pragma unroll
    for (int a = 0; a < 4; ++a)
#pragma unroll
        for (int b = 0; b < 4; ++b)
#pragma unroll
            for (int c = 0; c < 4; ++c) acc[a][b][c] = 0.f;

    float4 Ap[8]; float Bp[4][4];
#pragma unroll
    for (int j = 0; j < 8; ++j) Ap[j] = __ldg((const float4*)ar[j]);
#pragma unroll
    for (int nt = 0; nt < 4; ++nt)
#pragma unroll
        for (int j = 0; j < 4; ++j) Bp[nt][j] = __ldcg(br[nt] + j * 64);

    for (int g = 0; g < G; ++g) {
        float4 A[8]; float Bv[4][4];
#pragma unroll
        for (int j = 0; j < 8; ++j) A[j] = Ap[j];
#pragma unroll
        for (int nt = 0; nt < 4; ++nt)
#pragma unroll
            for (int j = 0; j < 4; ++j) Bv[nt][j] = Bp[nt][j];
        if (g + 1 < G) {
            int ko = (g + 1) * 16;
#pragma unroll
            for (int j = 0; j < 8; ++j) Ap[j] = __ldg((const float4*)(ar[j] + ko));
#pragma unroll
            for (int nt = 0; nt < 4; ++nt)
#pragma unroll
                for (int j = 0; j < 4; ++j) Bp[nt][j] = __ldcg(br[nt] + (ko + j) * 64);
        }
        uint32_t Au[8][4], Bu[4][4];
#pragma unroll
        for (int j = 0; j < 8; ++j) {
            Au[j][0] = tf32c(A[j].x); Au[j][1] = tf32c(A[j].y);
            Au[j][2] = tf32c(A[j].z); Au[j][3] = tf32c(A[j].w);
        }
#pragma unroll
        for (int nt = 0; nt < 4; ++nt)
#pragma unroll
            for (int j = 0; j < 4; ++j) Bu[nt][j] = tf32c(Bv[nt][j]);
#pragma unroll
        for (int mt = 0; mt < 4; ++mt)
#pragma unroll
            for (int nt = 0; nt < 4; ++nt) {
                mma8(acc[mt][nt], Au[mt*2][0], Au[mt*2+1][0], Au[mt*2][1], Au[mt*2+1][1],
                     Bu[nt][0], Bu[nt][1]);
                mma8(acc[mt][nt], Au[mt*2][2], Au[mt*2+1][2], Au[mt*2][3], Au[mt*2+1][3],
                     Bu[nt][2], Bu[nt][3]);
            }
    }

    __syncthreads();
    if (kw == 0) {
#pragma unroll
        for (int mt = 0; mt < 4; ++mt)
#pragma unroll
            for (int nt = 0; nt < 4; ++nt) {
                int m = mw * 64 + mt * 16 + qr, bc = nw * 32 + nt * 8 + q * 2;
                *(float2*)&sg[m * 72 + bc]       = make_float2(acc[mt][nt][0], acc[mt][nt][1]);
                *(float2*)&sg[(m + 8) * 72 + bc] = make_float2(acc[mt][nt][2], acc[mt][nt][3]);
            }
    }
    __syncthreads();
    if (kw == 1) {
#pragma unroll
        for (int mt = 0; mt < 4; ++mt)
#pragma unroll
            for (int nt = 0; nt < 4; ++nt) {
                int m = mw * 64 + mt * 16 + qr, bc = nw * 32 + nt * 8 + q * 2;
                float2 v0 = *(float2*)&sg[m * 72 + bc];
                float2 v1 = *(float2*)&sg[(m + 8) * 72 + bc];
                v0.x += acc[mt][nt][0]; v0.y += acc[mt][nt][1];
                v1.x += acc[mt][nt][2]; v1.y += acc[mt][nt][3];
                *(float2*)&sg[m * 72 + bc]       = v0;
                *(float2*)&sg[(m + 8) * 72 + bc] = v1;
            }
    }
    __syncthreads();
}

__global__ void k_init(const float* __restrict__ gu) {
    int n  = gridDim.x * blockDim.x;
    int id = blockIdx.x * blockDim.x + threadIdx.x;
    for (int q = id; q < B_ * L_; q += n) {
        int b = q >> 9, t = q & 511;
        float a0 = -logf(-logf(gu[q * 2 + 0]));
        float a1 = -logf(-logf(gu[q * 2 + 1]));
        float m  = fmaxf(a0, a1);
        float e0 = expf(a0 - m), e1 = expf(a1 - m);
        float inv = 1.0f / (e0 + e1);
        g_r[(t * B_ + b) * 2 + 0] = e0 * inv;
        g_r[(t * B_ + b) * 2 + 1] = e1 * inv;
    }
    for (int q = id; q < 2 * HL_ * B_; q += n) g_h[q] = 0.f;
    for (int q = id; q < 2 * HS_ * B_; q += n) g_hsm[q] = 0.f;
    for (int q = id; q < HL_ * B_; q += n) g_c[q] = 0.f;
    for (int q = id; q < HS_ * B_; q += n) g_cs[q] = 0.f;
}

template <int NTOT>
__global__ void __launch_bounds__(256)
k_ingemm(const int* __restrict__ x, const float* __restrict__ emb,
         const float* __restrict__ Wih, const float* __restrict__ bih,
         const float* __restrict__ bhh, float* __restrict__ out)
{
    __shared__ __align__(16) float Asd[32][130];
    __shared__ __align__(16) float Wst[32][138];
    __shared__ int toks[64];
    int tid = threadIdx.x, warp = tid >> 5, lane = tid & 31;
    int t = blockIdx.y, j0 = blockIdx.x * 128, b0 = warp * 8;

    if (tid < 64) toks[tid] = x[tid * L_ + t];
    __syncthreads();
    ull acc[8][2];
#pragma unroll
    for (int r = 0; r < 8; ++r) { acc[r][0] = 0ull; acc[r][1] = 0ull; }
    float ph[8], pw[16];
#pragma unroll
    for (int s = 0; s < 8; ++s) { int i = tid + s * 256, mm = i >> 5, kk = i & 31;
        ph[s] = __ldg(&emb[(size_t)toks[mm] * E_ + kk]); }
#pragma unroll
    for (int s = 0; s < 16; ++s) { int i = tid + s * 256, jj = i >> 5, kk = i & 31;
        pw[s] = __ldg(&Wih[(size_t)(j0 + jj) * E_ + kk]); }

    for (int ch = 0; ch < E_ / 32; ++ch) {
#pragma unroll
        for (int s = 0; s < 8; ++s) { int i = tid + s * 256, mm = i >> 5, kk = i & 31;
            *(float2*)&Asd[kk][mm * 2] = make_float2(ph[s], ph[s]); }
#pragma unroll
        for (int s = 0; s < 16; ++s) { int i = tid + s * 256, jj = i >> 5, kk = i & 31;
            Wst[kk][jj] = pw[s]; }
        __syncthreads();
        if (ch + 1 < E_ / 32) {
            int ks = (ch + 1) * 32;
#pragma unroll
            for (int s = 0; s < 8; ++s) { int i = tid + s * 256, mm = i >> 5, kk = i & 31;
                ph[s] = __ldg(&emb[(size_t)toks[mm] * E_ + ks + kk]); }
#pragma unroll
            for (int s = 0; s < 16; ++s) { int i = tid + s * 256, jj = i >> 5, kk = i & 31;
                pw[s] = __ldg(&Wih[(size_t)(j0 + jj) * E_ + ks + kk]); }
        }
#pragma unroll 4
        for (int kk = 0; kk < 32; ++kk) {
            ull w0 = *(const ull*)&Wst[kk][lane * 2];
            ull w1 = *(const ull*)&Wst[kk][lane * 2 + 64];
#pragma unroll
            for (int r = 0; r < 8; ++r) {
                ull av = *(const ull*)&Asd[kk][(b0 + r) * 2];
                FMA2(acc[r][0], av, w0, acc[r][0]);
                FMA2(acc[r][1], av, w1, acc[r][1]);
            }
        }
        __syncthreads();
    }
#pragma unroll
    for (int c = 0; c < 2; ++c) {
        int j = j0 + lane * 2 + 64 * c;
        float2 bi = *(const float2*)&bih[j];
        float2 bh = *(const float2*)&bhh[j];
        float bx = bi.x + bh.x, by = bi.y + bh.y;
#pragma unroll
        for (int r = 0; r < 8; ++r) {
            F2U u; u.u = acc[r][c];
            out[((size_t)t * NTOT + j)     * 64 + b0 + r] = u.f.x + bx;
            out[((size_t)t * NTOT + j + 1) * 64 + b0 + r] = u.f.y + by;
        }
    }
}

__global__ void __launch_bounds__(256)
k_pe(const int* __restrict__ x, const float* __restrict__ emb,
     const float* __restrict__ Wp, const float* __restrict__ bp, float* __restrict__ out_p)
{
    int gw = (blockIdx.x * blockDim.x + threadIdx.x) >> 5;
    int lane = threadIdx.x & 31;
    if (gw >= B_ * L_) return;
    const float* e = emb + (size_t)x[gw] * E_;
    float s0 = 0.f, s1 = 0.f;
    for (int k = lane; k < E_; k += 32) {
        float ev = e[k];
        s0 += ev * Wp[k];
        s1 += ev * Wp[2560 + k];
    }
#pragma unroll
    for (int o = 16; o; o >>= 1) {
        s0 += __shfl_down_sync(0xffffffffu, s0, o);
        s1 += __shfl_down_sync(0xffffffffu, s1, o);
    }
    if (lane == 0) {
        out_p[(size_t)gw * 2 + 0] = s0 + bp[0];
        out_p[(size_t)gw * 2 + 1] = s1 + bp[1];
    }
}

#define SG_  0
#define SHS_ 9216
#define SCS_ 11520
#define SPP_ 13824
#define SMEM_REC (14336 * 4)

__global__ void __launch_bounds__(256, 1)
k_rec(const float* __restrict__ Whl, const float* __restrict__ Whs,
      const float* __restrict__ Wp,  float* __restrict__ out_h, float* __restrict__ out_p)
{
    extern __shared__ float sh[];
    float* sg  = sh + SG_;
    float* shs = sh + SHS_;
    float* scs = sh + SCS_;
    float* spp = sh + SPP_;
    const int tid = threadIdx.x, n = blockIdx.x, k0 = n * 32;
    const int b = tid & 63, kq = tid >> 6;

    for (int t = 0; t < L_; ++t) {
        const float* hcur = g_h   + (size_t)(t & 1) * HL_ * B_;
        const float* scur = g_hsm + (size_t)(t & 1) * HS_ * B_;
        float* hnxt = g_h   + (size_t)((t + 1) & 1) * HL_ * B_;
        float* snxt = g_hsm + (size_t)((t + 1) & 1) * HS_ * B_;

        if (n < 8) {
            rec_gemm(Whs, scur, k0, HS_, 8, sg, tid);
            const float* gsb = g_gs + (size_t)t * 4 * HS_ * B_;
#pragma unroll 2
            for (int i = 0; i < 8; ++i) {
                int ki = kq * 8 + i, k = k0 + ki;
                float gi = sg[(0  + ki) * 72 + b] + __ldg(&gsb[(0 * HS_ + k) * 64 + b]);
                float gf = sg[(32 + ki) * 72 + b] + __ldg(&gsb[(1 * HS_ + k) * 64 + b]);
                float gg = sg[(64 + ki) * 72 + b] + __ldg(&gsb[(2 * HS_ + k) * 64 + b]);
                float go = sg[(96 + ki) * 72 + b] + __ldg(&gsb[(3 * HS_ + k) * 64 + b]);
                float co = g_cs[k * 64 + b];
                float cn = sigf(gf) * co + sigf(gi) * tanhf(gg);
                float hn = sigf(go) * tanhf(cn);
                g_cs[k * 64 + b] = cn;
                snxt[k * 64 + b] = hn;
                shs[ki * 72 + b] = hn;
                scs[ki * 72 + b] = cn;
            }
        }

        rec_gemm(Whl, hcur, k0, HL_, 32, sg, tid);

        float p0 = 0.f, p1 = 0.f, hx8[8];
        {
            const float* glb = g_gl + (size_t)t * 4 * HL_ * B_;
            float r0 = g_r[(t * B_ + b) * 2 + 0];
            float r1 = g_r[(t * B_ + b) * 2 + 1];
#pragma unroll 2
            for (int i = 0; i < 8; ++i) {
                int ki = kq * 8 + i, k = k0 + ki;
                float gi = sg[(0  + ki) * 72 + b] + __ldg(&glb[(0 * HL_ + k) * 64 + b]);
                float gf = sg[(32 + ki) * 72 + b] + __ldg(&glb[(1 * HL_ + k) * 64 + b]);
                float gg = sg[(64 + ki) * 72 + b] + __ldg(&glb[(2 * HL_ + k) * 64 + b]);
                float go = sg[(96 + ki) * 72 + b] + __ldg(&glb[(3 * HL_ + k) * 64 + b]);
                float co = g_c[k * 64 + b];
                float cn = sigf(gf) * co + sigf(gi) * tanhf(gg);
                float hn = sigf(go) * tanhf(cn);
                float hb, cb;
                if (n < 8) { hb = shs[ki * 72 + b]; cb = scs[ki * 72 + b]; }
                else       { hb = __ldcg(&hcur[k * 64 + b]); cb = cn; }
                float hx = r0 * hn + r1 * hb;
                float cx = r0 * cn + r1 * cb;
                g_c[k * 64 + b] = cx;
                hnxt[k * 64 + b] = hx;
                hx8[i] = hx;
                p0 += hn * __ldg(&Wp[E_ + k]) + cn * __ldg(&Wp[E_ + HL_ + k]);
                p1 += hn * __ldg(&Wp[2560 + E_ + k]) + cn * __ldg(&Wp[2560 + E_ + HL_ + k]);
            }
        }
        spp[2 * tid] = p0; spp[2 * tid + 1] = p1;
        __syncthreads();
        if (tid < 64) {
            float P0 = spp[2 * tid] + spp[2 * (tid + 64)] + spp[2 * (tid + 128)] + spp[2 * (tid + 192)];
            float P1 = spp[2 * tid + 1] + spp[2 * (tid + 64) + 1] + spp[2 * (tid + 128) + 1] + spp[2 * (tid + 192) + 1];
            atomicAdd(&out_p[((size_t)tid * L_ + t) * 2 + 0], P0);
            atomicAdd(&out_p[((size_t)tid * L_ + t) * 2 + 1], P1);
        }
        __syncthreads();
#pragma unroll
        for (int i = 0; i < 8; ++i) sg[(kq * 8 + i) * 72 + b] = hx8[i];
        __syncthreads();
        for (int idx = tid; idx < 2048; idx += 256) {
            int kk = idx & 31, bb = idx >> 5;
            out_h[((size_t)bb * L_ + t) * HL_ + k0 + kk] = sg[kk * 72 + bb];
        }
        grid_sync();
    }
}

__global__ void __launch_bounds__(256)
k_cls(const float* __restrict__ Wc1, const float* __restrict__ bc1,
      const float* __restrict__ Wc2, const float* __restrict__ bc2,
      float* __restrict__ out_logits)
{
    __shared__ float hb[1024];
    __shared__ float zs[512];
    __shared__ float lg[NC_];
    int b = blockIdx.x, tid = threadIdx.x;
    for (int i = tid; i < HL_; i += 256) hb[i] = fmaxf(g_h[i * 64 + b], 0.f);
    __syncthreads();
    for (int m = tid; m < 512; m += 256) {
        float acc = bc1[m];
        const float* w = Wc1 + (size_t)m * HL_;
        for (int k = 0; k < HL_; ++k) acc += hb[k] * w[k];
        zs[m] = fmaxf(acc, 0.f);
    }
    __syncthreads();
    if (tid < NC_) {
        float acc = bc2[tid];
        const float* w = Wc2 + (size_t)tid * 512;
        for (int m = 0; m < 512; ++m) acc += zs[m] * w[m];
        lg[tid] = acc;
    }
    __syncthreads();
    if (tid == 0) {
        float mx = lg[0];
        for (int nn = 1; nn < NC_; ++nn) mx = fmaxf(mx, lg[nn]);
        float e[NC_], s = 0.f;
        for (int nn = 0; nn < NC_; ++nn) { e[nn] = expf(lg[nn] - mx); s += e[nn]; }
        float inv = 1.f / s;
        for (int nn = 0; nn < NC_; ++nn) out_logits[b * NC_ + nn] = e[nn] * inv;
    }
}

__global__ void k_psoft(float* __restrict__ out_p) {
    int q = blockIdx.x * blockDim.x + threadIdx.x;
    if (q >= B_ * L_) return;
    float p0 = out_p[q * 2], p1 = out_p[q * 2 + 1];
    float m = fmaxf(p0, p1);
    float e0 = expf(p0 - m), e1 = expf(p1 - m);
    float inv = 1.f / (e0 + e1);
    out_p[q * 2 + 0] = e0 * inv;
    out_p[q * 2 + 1] = e1 * inv;
}

extern "C" void kernel_launch(void* const* d_in, const int* in_sizes, int n_in,
                              void* d_out, int out_size)
{
    const int*   x    = (const int*)  d_in[0];
    const float* gu   = (const float*)d_in[1];
    const float* emb  = (const float*)d_in[2];
    const float* Wihl = (const float*)d_in[3];
    const float* Whhl = (const float*)d_in[4];
    const float* bihl = (const float*)d_in[5];
    const float* bhhl = (const float*)d_in[6];
    const float* Wihs = (const float*)d_in[7];
    const float* Whhs = (const float*)d_in[8];
    const float* bihs = (const float*)d_in[9];
    const float* bhhs = (const float*)d_in[10];
    const float* Wp   = (const float*)d_in[11];
    const float* bp   = (const float*)d_in[12];
    const float* Wc1  = (const float*)d_in[13];
    const float* bc1  = (const float*)d_in[14];
    const float* Wc2  = (const float*)d_in[15];
    const float* bc2  = (const float*)d_in[16];

    float* out_logits = (float*)d_out;
    float* out_h      = out_logits + (size_t)B_ * NC_;
    float* out_p      = out_h + (size_t)B_ * L_ * HL_;

    float* ggl; cudaGetSymbolAddress((void**)&ggl, g_gl);
    float* ggs; cudaGetSymbolAddress((void**)&ggs, g_gs);

    cudaFuncSetAttribute(k_rec, cudaFuncAttributeMaxDynamicSharedMemorySize, SMEM_REC);

    k_init<<<256, 256>>>(gu);
    {
        dim3 gl(4 * HL_ / 128, L_);
        k_ingemm<4 * HL_><<<gl, 256>>>(x, emb, Wihl, bihl, bhhl, ggl);
        dim3 gs(4 * HS_ / 128, L_);
        k_ingemm<4 * HS_><<<gs, 256>>>(x, emb, Wihs, bihs, bhhs, ggs);
    }
    k_pe<<<(B_ * L_ * 32 + 255) / 256, 256>>>(x, emb, Wp, bp, out_p);
    k_rec<<<32, 256, SMEM_REC>>>(Whhl, Whhs, Wp, out_h, out_p);
    k_cls<<<B_, 256>>>(Wc1, bc1, Wc2, bc2, out_logits);
    k_psoft<<<(B_ * L_ + 255) / 256, 256>>>(out_p);
}

// round 12
// speedup vs baseline: 1.1764x; 1.1764x over previous
#include <cuda_runtime.h>
#include <cstdint>

#define B_   64
#define L_   512
#define E_   512
#define HL_  1024
#define HS_  256
#define NC_  5

typedef unsigned long long ull;
#define FMA2(d, a, b, c) asm("fma.rn.f32x2 %0, %1, %2, %3;" : "=l"(d) : "l"(a), "l"(b), "l"(c))
union F2U { ull u; float2 f; };

// ---------- device scratch ----------
__device__ float g_gl[(size_t)L_ * B_ * 4 * HL_];   // gates large [t][b][4096] (input part, recurrent added atomically)
__device__ float g_gs[(size_t)L_ * B_ * 4 * HS_];   // gates small [t][b][1024]
__device__ float g_r [L_ * B_ * 2];                 // [t][b][2]
__device__ float g_h [2 * HL_ * B_];                // h_l double buffered [buf][k][b]
__device__ float g_hsv[HS_ * B_];                   // h_s [k][b] (single buffer)
__device__ float g_c  [HL_ * B_];                   // c_l [k][b]
__device__ float g_cs [HS_ * B_];                   // c_s [k][b]
__device__ unsigned g_sub[8];                       // split barrier arrival
__device__ unsigned g_main;
__device__ unsigned g_gen;
__device__ unsigned g_scnt[32];                     // large slice completion counters
__device__ unsigned g_sscnt[8];                     // small slice counters
__device__ unsigned g_sflag[8];                     // small-cell-ready flags

__device__ __forceinline__ float sigf(float x) { return 1.0f / (1.0f + expf(-x)); }

// ---------- init: counters, gumbel r, states ----------
__global__ void k_init(const float* __restrict__ gu) {
    int n  = gridDim.x * blockDim.x;
    int id = blockIdx.x * blockDim.x + threadIdx.x;
    if (id < 8)  g_sub[id] = 0;
    if (id < 32) g_scnt[id] = 0;
    if (id < 8)  { g_sscnt[id] = 0; g_sflag[id] = 0; }
    if (id == 0) { g_main = 0; g_gen = 0; }
    for (int q = id; q < B_ * L_; q += n) {            // q = b*L + t
        int b = q >> 9, t = q & 511;
        float a0 = -logf(-logf(gu[q * 2 + 0]));
        float a1 = -logf(-logf(gu[q * 2 + 1]));
        float m  = fmaxf(a0, a1);
        float e0 = expf(a0 - m), e1 = expf(a1 - m);
        float inv = 1.0f / (e0 + e1);
        g_r[(t * B_ + b) * 2 + 0] = e0 * inv;
        g_r[(t * B_ + b) * 2 + 1] = e1 * inv;
    }
    for (int q = id; q < 2 * HL_ * B_; q += n) g_h[q] = 0.f;
    for (int q = id; q < HL_ * B_; q += n) g_c[q] = 0.f;
    for (int q = id; q < HS_ * B_; q += n) { g_hsv[q] = 0.f; g_cs[q] = 0.f; }
}

// ---------- input-gate GEMM (FFMA2, proven), out layout [t][b][j] ----------
template <int NTOT>
__global__ void __launch_bounds__(256)
k_ingemm(const int* __restrict__ x, const float* __restrict__ emb,
         const float* __restrict__ Wih, const float* __restrict__ bih,
         const float* __restrict__ bhh, float* __restrict__ out)
{
    __shared__ __align__(16) float Asd[32][130];
    __shared__ __align__(16) float Wst[32][138];
    __shared__ int toks[64];
    int tid = threadIdx.x, warp = tid >> 5, lane = tid & 31;
    int t = blockIdx.y, j0 = blockIdx.x * 128, b0 = warp * 8;

    if (tid < 64) toks[tid] = x[tid * L_ + t];
    __syncthreads();
    ull acc[8][2];
#pragma unroll
    for (int r = 0; r < 8; ++r) { acc[r][0] = 0ull; acc[r][1] = 0ull; }
    float ph[8], pw[16];
#pragma unroll
    for (int s = 0; s < 8; ++s) { int i = tid + s * 256, mm = i >> 5, kk = i & 31;
        ph[s] = __ldg(&emb[(size_t)toks[mm] * E_ + kk]); }
#pragma unroll
    for (int s = 0; s < 16; ++s) { int i = tid + s * 256, jj = i >> 5, kk = i & 31;
        pw[s] = __ldg(&Wih[(size_t)(j0 + jj) * E_ + kk]); }

    for (int ch = 0; ch < E_ / 32; ++ch) {
#pragma unroll
        for (int s = 0; s < 8; ++s) { int i = tid + s * 256, mm = i >> 5, kk = i & 31;
            *(float2*)&Asd[kk][mm * 2] = make_float2(ph[s], ph[s]); }
#pragma unroll
        for (int s = 0; s < 16; ++s) { int i = tid + s * 256, jj = i >> 5, kk = i & 31;
            Wst[kk][jj] = pw[s]; }
        __syncthreads();
        if (ch + 1 < E_ / 32) {
            int ks = (ch + 1) * 32;
#pragma unroll
            for (int s = 0; s < 8; ++s) { int i = tid + s * 256, mm = i >> 5, kk = i & 31;
                ph[s] = __ldg(&emb[(size_t)toks[mm] * E_ + ks + kk]); }
#pragma unroll
            for (int s = 0; s < 16; ++s) { int i = tid + s * 256, jj = i >> 5, kk = i & 31;
                pw[s] = __ldg(&Wih[(size_t)(j0 + jj) * E_ + ks + kk]); }
        }
#pragma unroll 4
        for (int kk = 0; kk < 32; ++kk) {
            ull w0 = *(const ull*)&Wst[kk][lane * 2];
            ull w1 = *(const ull*)&Wst[kk][lane * 2 + 64];
#pragma unroll
            for (int r = 0; r < 8; ++r) {
                ull av = *(const ull*)&Asd[kk][(b0 + r) * 2];
                FMA2(acc[r][0], av, w0, acc[r][0]);
                FMA2(acc[r][1], av, w1, acc[r][1]);
            }
        }
        __syncthreads();
    }
#pragma unroll
    for (int c = 0; c < 2; ++c) {
        int j = j0 + lane * 2 + 64 * c;
        float2 bi = *(const float2*)&bih[j];
        float2 bh = *(const float2*)&bhh[j];
        float bx = bi.x + bh.x, by = bi.y + bh.y;
#pragma unroll
        for (int r = 0; r < 8; ++r) {
            F2U u; u.u = acc[r][c];
            *(float2*)&out[((size_t)t * B_ + b0 + r) * NTOT + j] =
                make_float2(u.f.x + bx, u.f.y + by);
        }
    }
}

// ---------- p_t embedding part ----------
__global__ void __launch_bounds__(256)
k_pe(const int* __restrict__ x, const float* __restrict__ emb,
     const float* __restrict__ Wp, const float* __restrict__ bp, float* __restrict__ out_p)
{
    int gw = (blockIdx.x * blockDim.x + threadIdx.x) >> 5;
    int lane = threadIdx.x & 31;
    if (gw >= B_ * L_) return;
    const float* e = emb + (size_t)x[gw] * E_;
    float s0 = 0.f, s1 = 0.f;
    for (int k = lane; k < E_; k += 32) {
        float ev = e[k];
        s0 += ev * Wp[k];
        s1 += ev * Wp[2560 + k];
    }
#pragma unroll
    for (int o = 16; o; o >>= 1) {
        s0 += __shfl_down_sync(0xffffffffu, s0, o);
        s1 += __shfl_down_sync(0xffffffffu, s1, o);
    }
    if (lane == 0) {
        out_p[(size_t)gw * 2 + 0] = s0 + bp[0];
        out_p[(size_t)gw * 2 + 1] = s1 + bp[1];
    }
}

// ---------- persistent recurrence: 144 CTAs, owner-does-phase2, 1 barrier/step ----------
// Tile map: large tile = (js in [0,32)) x (kpart in [0,4)); rows m in [0,128):
//   W row = (m>>5)*Kdim + 32*js + (m&31)  (gate-interleaved). Small: 8 slices x 2 kparts.
__global__ void __launch_bounds__(256, 1)
k_rec(const float* __restrict__ Whl, const float* __restrict__ Whs,
      const float* __restrict__ Wp,  float* __restrict__ out_h, float* __restrict__ out_p)
{
    __shared__ __align__(16) float Asd[32][130];
    __shared__ __align__(16) float Wst[32][138];
    __shared__ float sred[512];
    __shared__ int s_own;

    int tid = threadIdx.x, warp = tid >> 5, lane = tid & 31;
    int b0w = warp * 8;
    int tile = blockIdx.x;
    int big = (tile < 128);
    int js, ks0, nch, Kdim, H;
    const float* W;
    if (big) { js = tile >> 2; ks0 = (tile & 3) * 256; nch = 8; Kdim = HL_; H = 4096; W = Whl; }
    else     { int ts = tile - 128; js = ts >> 1; ks0 = (ts & 1) * 128; nch = 4; Kdim = HS_; H = 1024; W = Whs; }
    int ksl = js * 32;
    int bq = tid & 63, kq = tid >> 6;

    for (int t = 0; t < L_; ++t) {
        const float* hcur = g_h + (size_t)(t & 1) * HL_ * B_;
        float* hnxt = g_h + (size_t)((t + 1) & 1) * HL_ * B_;
        const float* hsrc = big ? hcur : g_hsv;

        // ---- phase 1: K-part GEMM ----
        ull acc[8][2];
#pragma unroll
        for (int r = 0; r < 8; ++r) { acc[r][0] = 0ull; acc[r][1] = 0ull; }
        float ph[8], pw[16];
#pragma unroll
        for (int s = 0; s < 8; ++s) { int i = tid + s * 256, kk = i >> 6, bb = i & 63;
            ph[s] = __ldcg(&hsrc[(ks0 + kk) * B_ + bb]); }
#pragma unroll
        for (int s = 0; s < 16; ++s) { int i = tid + s * 256, jj = i >> 5, kk = i & 31;
            int row = (jj >> 5) * Kdim + ksl + (jj & 31);
            pw[s] = __ldg(&W[(size_t)row * Kdim + ks0 + kk]); }

        for (int ch = 0; ch < nch; ++ch) {
#pragma unroll
            for (int s = 0; s < 8; ++s) { int i = tid + s * 256, kk = i >> 6, bb = i & 63;
                *(float2*)&Asd[kk][bb * 2] = make_float2(ph[s], ph[s]); }
#pragma unroll
            for (int s = 0; s < 16; ++s) { int i = tid + s * 256, jj = i >> 5, kk = i & 31;
                Wst[kk][jj] = pw[s]; }
            __syncthreads();
            if (ch + 1 < nch) {
                int ks = ks0 + (ch + 1) * 32;
#pragma unroll
                for (int s = 0; s < 8; ++s) { int i = tid + s * 256, kk = i >> 6, bb = i & 63;
                    ph[s] = __ldcg(&hsrc[(ks + kk) * B_ + bb]); }
#pragma unroll
                for (int s = 0; s < 16; ++s) { int i = tid + s * 256, jj = i >> 5, kk = i & 31;
                    int row = (jj >> 5) * Kdim + ksl + (jj & 31);
                    pw[s] = __ldg(&W[(size_t)row * Kdim + ks + kk]); }
            }
#pragma unroll 4
            for (int kk = 0; kk < 32; ++kk) {
                ull w0 = *(const ull*)&Wst[kk][lane * 2];
                ull w1 = *(const ull*)&Wst[kk][lane * 2 + 64];
#pragma unroll
                for (int r = 0; r < 8; ++r) {
                    ull av = *(const ull*)&Asd[kk][(b0w + r) * 2];
                    FMA2(acc[r][0], av, w0, acc[r][0]);
                    FMA2(acc[r][1], av, w1, acc[r][1]);
                }
            }
            __syncthreads();
        }
        {
            float* dst = big ? g_gl + (size_t)t * B_ * 4096 : g_gs + (size_t)t * B_ * 1024;
#pragma unroll
            for (int c = 0; c < 2; ++c) {
                int m = lane * 2 + 64 * c;
                int j = (m >> 5) * Kdim + ksl + (m & 31);
#pragma unroll
                for (int r = 0; r < 8; ++r) {
                    F2U u; u.u = acc[r][c];
                    atomicAdd(&dst[(size_t)(b0w + r) * H + j],     u.f.x);
                    atomicAdd(&dst[(size_t)(b0w + r) * H + j + 1], u.f.y);
                }
            }
        }

        // ---- slice ownership ----
        if (tid == 0) {
            __threadfence();
            unsigned o = atomicAdd(big ? &g_scnt[js] : &g_sscnt[js], 1u);
            s_own = big ? ((o & 3u) == 3u) : ((o & 1u) == 1u);
        }
        __syncthreads();

        if (s_own) {
            if (!big) {
                // small cell for k in [ksl, ksl+32)
                const float* gsb = g_gs + (size_t)t * B_ * 1024;
                __threadfence();   // order counter observation before reads
#pragma unroll 2
                for (int i = 0; i < 8; ++i) {
                    int k = ksl + kq * 8 + i;
                    float gi = __ldcg(&gsb[(size_t)bq * 1024 + k]);
                    float gf = __ldcg(&gsb[(size_t)bq * 1024 + 256 + k]);
                    float gg = __ldcg(&gsb[(size_t)bq * 1024 + 512 + k]);
                    float go = __ldcg(&gsb[(size_t)bq * 1024 + 768 + k]);
                    float co = __ldcg(&g_cs[k * 64 + bq]);
                    float cn = sigf(gf) * co + sigf(gi) * tanhf(gg);
                    float hn = sigf(go) * tanhf(cn);
                    g_cs[k * 64 + bq] = cn;
                    g_hsv[k * 64 + bq] = hn;
                }
                __threadfence();
                __syncthreads();
                if (tid == 0) atomicExch(&g_sflag[js], (unsigned)(t + 1));
            } else {
                if (js < 8) {
                    if (tid == 0) {
                        while (*(volatile unsigned*)&g_sflag[js] != (unsigned)(t + 1)) __nanosleep(32);
                    }
                    __syncthreads();
                }
                __threadfence();
                const float* glb = g_gl + (size_t)t * B_ * 4096;
                float r0 = g_r[(t * B_ + bq) * 2 + 0];
                float r1 = g_r[(t * B_ + bq) * 2 + 1];
                float p0 = 0.f, p1 = 0.f;
#pragma unroll 2
                for (int i = 0; i < 8; ++i) {
                    int k = ksl + kq * 8 + i;
                    float gi = __ldcg(&glb[(size_t)bq * 4096 + k]);
                    float gf = __ldcg(&glb[(size_t)bq * 4096 + 1024 + k]);
                    float gg = __ldcg(&glb[(size_t)bq * 4096 + 2048 + k]);
                    float go = __ldcg(&glb[(size_t)bq * 4096 + 3072 + k]);
                    float co = __ldcg(&g_c[k * 64 + bq]);
                    float cn = sigf(gf) * co + sigf(gi) * tanhf(gg);
                    float hn = sigf(go) * tanhf(cn);
                    float hb, cb;
                    if (js < 8) { hb = __ldcg(&g_hsv[k * 64 + bq]); cb = __ldcg(&g_cs[k * 64 + bq]); }
                    else        { hb = __ldcg(&hcur[k * 64 + bq]);  cb = cn; }
                    float hx = r0 * hn + r1 * hb;
                    float cx = r0 * cn + r1 * cb;
                    g_c[k * 64 + bq] = cx;
                    hnxt[k * 64 + bq] = hx;
                    out_h[((size_t)bq * L_ + t) * HL_ + k] = hx;
                    p0 += hn * __ldg(&Wp[512 + k])  + cn * __ldg(&Wp[1536 + k]);
                    p1 += hn * __ldg(&Wp[3072 + k]) + cn * __ldg(&Wp[4096 + k]);
                }
                sred[tid] = p0; sred[256 + tid] = p1;
                __threadfence();
                __syncthreads();
                if (tid < 64) {
                    float P0 = sred[tid] + sred[tid + 64] + sred[tid + 128] + sred[tid + 192];
                    float P1 = sred[256 + tid] + sred[256 + tid + 64] + sred[256 + tid + 128] + sred[256 + tid + 192];
                    atomicAdd(&out_p[((size_t)tid * L_ + t) * 2 + 0], P0);
                    atomicAdd(&out_p[((size_t)tid * L_ + t) * 2 + 1], P1);
                }
            }
        }

        // ---- single grid barrier (8-way split arrivals) ----
        __syncthreads();
        if (tid == 0) {
            __threadfence();
            unsigned o = atomicAdd(&g_sub[blockIdx.x & 7], 1u);
            if ((o % 18u) == 17u) {
                unsigned m2 = atomicAdd(&g_main, 1u);
                if ((m2 & 7u) == 7u) { __threadfence(); atomicAdd(&g_gen, 1u); }
            }
            while (*(volatile unsigned*)&g_gen < (unsigned)(t + 1)) __nanosleep(32);
            __threadfence();
        }
        __syncthreads();
    }
}

// ---------- classifier head (final h in g_h buffer 0, [k][b]) ----------
__global__ void __launch_bounds__(256)
k_cls(const float* __restrict__ Wc1, const float* __restrict__ bc1,
      const float* __restrict__ Wc2, const float* __restrict__ bc2,
      float* __restrict__ out_logits)
{
    __shared__ float hb[1024];
    __shared__ float zs[512];
    __shared__ float lg[NC_];
    int b = blockIdx.x, tid = threadIdx.x;
    for (int i = tid; i < HL_; i += 256) hb[i] = fmaxf(g_h[i * 64 + b], 0.f);
    __syncthreads();
    for (int m = tid; m < 512; m += 256) {
        float acc = bc1[m];
        const float* w = Wc1 + (size_t)m * HL_;
        for (int k = 0; k < HL_; ++k) acc += hb[k] * w[k];
        zs[m] = fmaxf(acc, 0.f);
    }
    __syncthreads();
    if (tid < NC_) {
        float acc = bc2[tid];
        const float* w = Wc2 + (size_t)tid * 512;
        for (int m = 0; m < 512; ++m) acc += zs[m] * w[m];
        lg[tid] = acc;
    }
    __syncthreads();
    if (tid == 0) {
        float mx = lg[0];
        for (int nn = 1; nn < NC_; ++nn) mx = fmaxf(mx, lg[nn]);
        float e[NC_], s = 0.f;
        for (int nn = 0; nn < NC_; ++nn) { e[nn] = expf(lg[nn] - mx); s += e[nn]; }
        float inv = 1.f / s;
        for (int nn = 0; nn < NC_; ++nn) out_logits[b * NC_ + nn] = e[nn] * inv;
    }
}

__global__ void k_psoft(float* __restrict__ out_p) {
    int q = blockIdx.x * blockDim.x + threadIdx.x;
    if (q >= B_ * L_) return;
    float p0 = out_p[q * 2], p1 = out_p[q * 2 + 1];
    float m = fmaxf(p0, p1);
    float e0 = expf(p0 - m), e1 = expf(p1 - m);
    float inv = 1.f / (e0 + e1);
    out_p[q * 2 + 0] = e0 * inv;
    out_p[q * 2 + 1] = e1 * inv;
}

// ---------- launch ----------
extern "C" void kernel_launch(void* const* d_in, const int* in_sizes, int n_in,
                              void* d_out, int out_size)
{
    const int*   x    = (const int*)  d_in[0];
    const float* gu   = (const float*)d_in[1];
    const float* emb  = (const float*)d_in[2];
    const float* Wihl = (const float*)d_in[3];
    const float* Whhl = (const float*)d_in[4];
    const float* bihl = (const float*)d_in[5];
    const float* bhhl = (const float*)d_in[6];
    const float* Wihs = (const float*)d_in[7];
    const float* Whhs = (const float*)d_in[8];
    const float* bihs = (const float*)d_in[9];
    const float* bhhs = (const float*)d_in[10];
    const float* Wp   = (const float*)d_in[11];
    const float* bp   = (const float*)d_in[12];
    const float* Wc1  = (const float*)d_in[13];
    const float* bc1  = (const float*)d_in[14];
    const float* Wc2  = (const float*)d_in[15];
    const float* bc2  = (const float*)d_in[16];

    float* out_logits = (float*)d_out;
    float* out_h      = out_logits + (size_t)B_ * NC_;
    float* out_p      = out_h + (size_t)B_ * L_ * HL_;

    float* ggl; cudaGetSymbolAddress((void**)&ggl, g_gl);
    float* ggs; cudaGetSymbolAddress((void**)&ggs, g_gs);

    k_init<<<256, 256>>>(gu);
    {
        dim3 gl(4 * HL_ / 128, L_);
        k_ingemm<4 * HL_><<<gl, 256>>>(x, emb, Wihl, bihl, bhhl, ggl);
        dim3 gs(4 * HS_ / 128, L_);
        k_ingemm<4 * HS_><<<gs, 256>>>(x, emb, Wihs, bihs, bhhs, ggs);
    }
    k_pe<<<(B_ * L_ * 32 + 255) / 256, 256>>>(x, emb, Wp, bp, out_p);
    k_rec<<<144, 256>>>(Whhl, Whhs, Wp, out_h, out_p);
    k_cls<<<B_, 256>>>(Wc1, bc1, Wc2, bc2, out_logits);
    k_psoft<<<(B_ * L_ + 255) / 256, 256>>>(out_p);
}

// round 13
// speedup vs baseline: 1.3333x; 1.1334x over previous
#include <cuda_runtime.h>
#include <cstdint>

#define B_   64
#define L_   512
#define E_   512
#define HL_  1024
#define HS_  256
#define NC_  5

typedef unsigned long long ull;
#define FMA2(d, a, b, c) asm("fma.rn.f32x2 %0, %1, %2, %3;" : "=l"(d) : "l"(a), "l"(b), "l"(c))
union F2U { ull u; float2 f; };

// ---------- device scratch ----------
__device__ float g_gl[(size_t)L_ * B_ * 4 * HL_];   // input gates large [t][b][4096]
__device__ float g_gs[(size_t)L_ * B_ * 4 * HS_];   // input gates small [t][b][1024]
__device__ float g_pl[8 * B_ * 4 * HL_];            // recurrent half-partials large [hp][b][4096]
__device__ float g_ps[4 * B_ * 4 * HS_];            // recurrent half-partials small [hp][b][1024]
__device__ float g_r [L_ * B_ * 2];
__device__ float g_hl[HL_ * B_];                    // states [k][b]
__device__ float g_cl[HL_ * B_];
__device__ float g_hs[HS_ * B_];
__device__ float g_cs[HS_ * B_];
__device__ unsigned g_bar_arrive = 0;
__device__ unsigned g_bar_gen = 0;

__device__ __forceinline__ float sigf(float x)  { return __fdividef(1.f, 1.f + __expf(-x)); }
__device__ __forceinline__ float tanhfa(float x){ return 1.f - __fdividef(2.f, __expf(2.f * x) + 1.f); }

__device__ __forceinline__ void grid_sync(void) {
    __syncthreads();
    if (threadIdx.x == 0) {
        unsigned gen = *((volatile unsigned*)&g_bar_gen);
        __threadfence();
        unsigned a = atomicAdd(&g_bar_arrive, 1u);
        if (a == gridDim.x - 1) {
            g_bar_arrive = 0; __threadfence(); atomicAdd(&g_bar_gen, 1u);
        } else {
            while (*((volatile unsigned*)&g_bar_gen) == gen) { __nanosleep(32); }
        }
        __threadfence();
    }
    __syncthreads();
}

// ---------- init ----------
__global__ void k_init(const float* __restrict__ gu) {
    int n  = gridDim.x * blockDim.x;
    int id = blockIdx.x * blockDim.x + threadIdx.x;
    for (int q = id; q < B_ * L_; q += n) {            // q = b*L + t
        int b = q >> 9, t = q & 511;
        float a0 = -logf(-logf(gu[q * 2 + 0]));
        float a1 = -logf(-logf(gu[q * 2 + 1]));
        float m  = fmaxf(a0, a1);
        float e0 = expf(a0 - m), e1 = expf(a1 - m);
        float inv = 1.0f / (e0 + e1);
        g_r[(t * B_ + b) * 2 + 0] = e0 * inv;
        g_r[(t * B_ + b) * 2 + 1] = e1 * inv;
    }
    for (int q = id; q < HL_ * B_; q += n) { g_hl[q] = 0.f; g_cl[q] = 0.f; }
    for (int q = id; q < HS_ * B_; q += n) { g_hs[q] = 0.f; g_cs[q] = 0.f; }
}

// ---------- input-gate GEMM (FFMA2, proven), out layout [t][b][j] ----------
template <int NTOT>
__global__ void __launch_bounds__(256)
k_ingemm(const int* __restrict__ x, const float* __restrict__ emb,
         const float* __restrict__ Wih, const float* __restrict__ bih,
         const float* __restrict__ bhh, float* __restrict__ out)
{
    __shared__ __align__(16) float Asd[32][130];
    __shared__ __align__(16) float Wst[32][138];
    __shared__ int toks[64];
    int tid = threadIdx.x, warp = tid >> 5, lane = tid & 31;
    int m0 = blockIdx.y * 64, j0 = blockIdx.x * 128, b0 = warp * 8;

    if (tid < 64) { int m = m0 + tid; toks[tid] = x[(m & 63) * L_ + (m >> 6)]; }
    __syncthreads();
    ull acc[8][2];
#pragma unroll
    for (int r = 0; r < 8; ++r) { acc[r][0] = 0ull; acc[r][1] = 0ull; }
    float ph[8], pw[16];
#pragma unroll
    for (int s = 0; s < 8; ++s) { int i = tid + s * 256, mm = i >> 5, kk = i & 31;
        ph[s] = __ldg(&emb[(size_t)toks[mm] * E_ + kk]); }
#pragma unroll
    for (int s = 0; s < 16; ++s) { int i = tid + s * 256, jj = i >> 5, kk = i & 31;
        pw[s] = __ldg(&Wih[(size_t)(j0 + jj) * E_ + kk]); }

    for (int ch = 0; ch < E_ / 32; ++ch) {
#pragma unroll
        for (int s = 0; s < 8; ++s) { int i = tid + s * 256, mm = i >> 5, kk = i & 31;
            *(float2*)&Asd[kk][mm * 2] = make_float2(ph[s], ph[s]); }
#pragma unroll
        for (int s = 0; s < 16; ++s) { int i = tid + s * 256, jj = i >> 5, kk = i & 31;
            Wst[kk][jj] = pw[s]; }
        __syncthreads();
        if (ch + 1 < E_ / 32) {
            int ks = (ch + 1) * 32;
#pragma unroll
            for (int s = 0; s < 8; ++s) { int i = tid + s * 256, mm = i >> 5, kk = i & 31;
                ph[s] = __ldg(&emb[(size_t)toks[mm] * E_ + ks + kk]); }
#pragma unroll
            for (int s = 0; s < 16; ++s) { int i = tid + s * 256, jj = i >> 5, kk = i & 31;
                pw[s] = __ldg(&Wih[(size_t)(j0 + jj) * E_ + ks + kk]); }
        }
#pragma unroll 4
        for (int kk = 0; kk < 32; ++kk) {
            ull w0 = *(const ull*)&Wst[kk][lane * 2];
            ull w1 = *(const ull*)&Wst[kk][lane * 2 + 64];
#pragma unroll
            for (int r = 0; r < 8; ++r) {
                ull av = *(const ull*)&Asd[kk][(b0 + r) * 2];
                FMA2(acc[r][0], av, w0, acc[r][0]);
                FMA2(acc[r][1], av, w1, acc[r][1]);
            }
        }
        __syncthreads();
    }
#pragma unroll
    for (int c = 0; c < 2; ++c) {
        int j = j0 + lane * 2 + 64 * c;
        float2 bi = *(const float2*)&bih[j];
        float2 bh = *(const float2*)&bhh[j];
        float bx = bi.x + bh.x, by = bi.y + bh.y;
#pragma unroll
        for (int r = 0; r < 8; ++r) {
            F2U u; u.u = acc[r][c];
            *(float2*)&out[(size_t)(m0 + b0 + r) * NTOT + j] = make_float2(u.f.x + bx, u.f.y + by);
        }
    }
}

// ---------- p_t embedding part ----------
__global__ void __launch_bounds__(256)
k_pe(const int* __restrict__ x, const float* __restrict__ emb,
     const float* __restrict__ Wp, const float* __restrict__ bp, float* __restrict__ out_p)
{
    int gw = (blockIdx.x * blockDim.x + threadIdx.x) >> 5;
    int lane = threadIdx.x & 31;
    if (gw >= B_ * L_) return;
    const float* e = emb + (size_t)x[gw] * E_;
    float s0 = 0.f, s1 = 0.f;
    for (int k = lane; k < E_; k += 32) {
        float ev = e[k];
        s0 += ev * Wp[k];
        s1 += ev * Wp[2560 + k];
    }
#pragma unroll
    for (int o = 16; o; o >>= 1) {
        s0 += __shfl_down_sync(0xffffffffu, s0, o);
        s1 += __shfl_down_sync(0xffffffffu, s1, o);
    }
    if (lane == 0) {
        out_p[(size_t)gw * 2 + 0] = s0 + bp[0];
        out_p[(size_t)gw * 2 + 1] = s1 + bp[1];
    }
}

// ---------- persistent recurrence: 144 CTAs x 512 thr (2 warpgroups split K) ----------
#define SMEM_REC (2 * 8576 * 4)   /* per-wg Asd(32x130)+Wst(32x138) floats */

__global__ void __launch_bounds__(512, 1)
k_rec(const float* __restrict__ Whl, const float* __restrict__ Whs,
      const float* __restrict__ Wp,  float* __restrict__ out_h, float* __restrict__ out_p)
{
    extern __shared__ float sm[];
    int tid = threadIdx.x;
    int wg = tid >> 8, wt = tid & 255;
    int warp = wt >> 5, lane = wt & 31, b0 = warp * 8;
    float* As = sm + wg * 8576;          // [32][130]
    float* Ws = As + 4160;               // [32][138]

    int tile = blockIdx.x, big = tile < 128;
    int j0, ks0, nchw, Kdim, H;
    const float *W, *hsrc;
    float* pdst;
    if (big) { j0 = (tile >> 2) * 128; ks0 = (tile & 3) * 256; nchw = 4; Kdim = HL_; H = 4096;
               W = Whl; hsrc = g_hl;
               pdst = g_pl + (size_t)((tile & 3) * 2 + wg) * B_ * 4096; }
    else { int ts = tile - 128; j0 = (ts >> 1) * 128; ks0 = (ts & 1) * 128; nchw = 2; Kdim = HS_; H = 1024;
           W = Whs; hsrc = g_hs;
           pdst = g_ps + (size_t)((ts & 1) * 2 + wg) * B_ * 1024; }
    int ksw = ks0 + wg * nchw * 32;      // this warpgroup's K start
    int gtid = blockIdx.x * 512 + tid;

    for (int t = 0; t < L_; ++t) {
        // ---- phase 1: half-K GEMM ----
        ull acc[8][2];
#pragma unroll
        for (int r = 0; r < 8; ++r) { acc[r][0] = 0ull; acc[r][1] = 0ull; }
        float ph[8], pw[16];
#pragma unroll
        for (int s = 0; s < 8; ++s) { int i = wt + s * 256, kk = i >> 6, bb = i & 63;
            ph[s] = __ldcg(&hsrc[(ksw + kk) * B_ + bb]); }
#pragma unroll
        for (int s = 0; s < 16; ++s) { int i = wt + s * 256, jj = i >> 5, kk = i & 31;
            pw[s] = __ldg(&W[(size_t)(j0 + jj) * Kdim + ksw + kk]); }

        for (int ch = 0; ch < nchw; ++ch) {
#pragma unroll
            for (int s = 0; s < 8; ++s) { int i = wt + s * 256, kk = i >> 6, bb = i & 63;
                *(float2*)&As[kk * 130 + bb * 2] = make_float2(ph[s], ph[s]); }
#pragma unroll
            for (int s = 0; s < 16; ++s) { int i = wt + s * 256, jj = i >> 5, kk = i & 31;
                Ws[kk * 138 + jj] = pw[s]; }
            __syncthreads();
            if (ch + 1 < nchw) {
                int ks = ksw + (ch + 1) * 32;
#pragma unroll
                for (int s = 0; s < 8; ++s) { int i = wt + s * 256, kk = i >> 6, bb = i & 63;
                    ph[s] = __ldcg(&hsrc[(ks + kk) * B_ + bb]); }
#pragma unroll
                for (int s = 0; s < 16; ++s) { int i = wt + s * 256, jj = i >> 5, kk = i & 31;
                    pw[s] = __ldg(&W[(size_t)(j0 + jj) * Kdim + ks + kk]); }
            }
#pragma unroll 4
            for (int kk = 0; kk < 32; ++kk) {
                ull w0 = *(const ull*)&Ws[kk * 138 + lane * 2];
                ull w1 = *(const ull*)&Ws[kk * 138 + lane * 2 + 64];
#pragma unroll
                for (int r = 0; r < 8; ++r) {
                    ull av = *(const ull*)&As[kk * 130 + (b0 + r) * 2];
                    FMA2(acc[r][0], av, w0, acc[r][0]);
                    FMA2(acc[r][1], av, w1, acc[r][1]);
                }
            }
            __syncthreads();
        }
        // store half-partials (plain coalesced stores, no atomics)
#pragma unroll
        for (int c = 0; c < 2; ++c) {
            int j = j0 + lane * 2 + 64 * c;
#pragma unroll
            for (int r = 0; r < 8; ++r) {
                F2U u; u.u = acc[r][c];
                *(float2*)&pdst[(size_t)(b0 + r) * H + j] = u.f;
            }
        }
        grid_sync();

        // ---- phase 2: fused cells + blend + p_t ----
        for (int idx = gtid; idx < B_ * HL_; idx += 144 * 512) {
            int b = idx >> 10, k = idx & 1023;
            const float* gl = g_gl + ((size_t)t * B_ + b) * 4096;
            float gv[4];
#pragma unroll
            for (int g = 0; g < 4; ++g) {
                float v = __ldcg(&gl[g * 1024 + k]);
#pragma unroll
                for (int p = 0; p < 8; ++p)
                    v += __ldcg(&g_pl[(size_t)p * B_ * 4096 + (size_t)b * 4096 + g * 1024 + k]);
                gv[g] = v;
            }
            float c_old = __ldcg(&g_cl[k * B_ + b]);
            float h_old = __ldcg(&g_hl[k * B_ + b]);
            float c_new = sigf(gv[1]) * c_old + sigf(gv[0]) * tanhfa(gv[2]);
            float h_new = sigf(gv[3]) * tanhfa(c_new);

            float h_bl, c_bl;
            if (k < HS_) {
                const float* gs = g_gs + ((size_t)t * B_ + b) * 1024;
                float sv[4];
#pragma unroll
                for (int g = 0; g < 4; ++g) {
                    float v = __ldcg(&gs[g * 256 + k]);
#pragma unroll
                    for (int p = 0; p < 4; ++p)
                        v += __ldcg(&g_ps[(size_t)p * B_ * 1024 + (size_t)b * 1024 + g * 256 + k]);
                    sv[g] = v;
                }
                float cs_old = __ldcg(&g_cs[k * B_ + b]);
                float cs_new = sigf(sv[1]) * cs_old + sigf(sv[0]) * tanhfa(sv[2]);
                float hs_new = sigf(sv[3]) * tanhfa(cs_new);
                g_cs[k * B_ + b] = cs_new;
                g_hs[k * B_ + b] = hs_new;
                h_bl = hs_new; c_bl = cs_new;
            } else {
                h_bl = h_old;
                c_bl = c_new;
            }
            float r0 = g_r[(t * B_ + b) * 2 + 0];
            float r1 = g_r[(t * B_ + b) * 2 + 1];
            float h_next = r0 * h_new + r1 * h_bl;
            float c_next = r0 * c_new + r1 * c_bl;
            g_hl[k * B_ + b] = h_next;
            g_cl[k * B_ + b] = c_next;
            out_h[((size_t)b * L_ + t) * HL_ + k] = h_next;

            float p0 = h_new * __ldg(&Wp[512 + k])  + c_new * __ldg(&Wp[1536 + k]);
            float p1 = h_new * __ldg(&Wp[3072 + k]) + c_new * __ldg(&Wp[4096 + k]);
#pragma unroll
            for (int o = 16; o; o >>= 1) {
                p0 += __shfl_down_sync(0xffffffffu, p0, o);
                p1 += __shfl_down_sync(0xffffffffu, p1, o);
            }
            if ((tid & 31) == 0) {
                atomicAdd(&out_p[((size_t)b * L_ + t) * 2 + 0], p0);
                atomicAdd(&out_p[((size_t)b * L_ + t) * 2 + 1], p1);
            }
        }
        grid_sync();
    }
}

// ---------- classifier head ----------
__global__ void __launch_bounds__(256)
k_cls(const float* __restrict__ Wc1, const float* __restrict__ bc1,
      const float* __restrict__ Wc2, const float* __restrict__ bc2,
      float* __restrict__ out_logits)
{
    __shared__ float hb[1024];
    __shared__ float zs[512];
    __shared__ float lg[NC_];
    int b = blockIdx.x, tid = threadIdx.x;
    for (int i = tid; i < HL_; i += 256) hb[i] = fmaxf(g_hl[i * B_ + b], 0.f);
    __syncthreads();
    for (int m = tid; m < 512; m += 256) {
        float acc = bc1[m];
        const float* w = Wc1 + (size_t)m * HL_;
        for (int k = 0; k < HL_; ++k) acc += hb[k] * w[k];
        zs[m] = fmaxf(acc, 0.f);
    }
    __syncthreads();
    if (tid < NC_) {
        float acc = bc2[tid];
        const float* w = Wc2 + (size_t)tid * 512;
        for (int m = 0; m < 512; ++m) acc += zs[m] * w[m];
        lg[tid] = acc;
    }
    __syncthreads();
    if (tid == 0) {
        float mx = lg[0];
        for (int nn = 1; nn < NC_; ++nn) mx = fmaxf(mx, lg[nn]);
        float e[NC_], s = 0.f;
        for (int nn = 0; nn < NC_; ++nn) { e[nn] = expf(lg[nn] - mx); s += e[nn]; }
        float inv = 1.f / s;
        for (int nn = 0; nn < NC_; ++nn) out_logits[b * NC_ + nn] = e[nn] * inv;
    }
}

__global__ void k_psoft(float* __restrict__ out_p) {
    int q = blockIdx.x * blockDim.x + threadIdx.x;
    if (q >= B_ * L_) return;
    float p0 = out_p[q * 2], p1 = out_p[q * 2 + 1];
    float m = fmaxf(p0, p1);
    float e0 = expf(p0 - m), e1 = expf(p1 - m);
    float inv = 1.f / (e0 + e1);
    out_p[q * 2 + 0] = e0 * inv;
    out_p[q * 2 + 1] = e1 * inv;
}

// ---------- launch ----------
extern "C" void kernel_launch(void* const* d_in, const int* in_sizes, int n_in,
                              void* d_out, int out_size)
{
    const int*   x    = (const int*)  d_in[0];
    const float* gu   = (const float*)d_in[1];
    const float* emb  = (const float*)d_in[2];
    const float* Wihl = (const float*)d_in[3];
    const float* Whhl = (const float*)d_in[4];
    const float* bihl = (const float*)d_in[5];
    const float* bhhl = (const float*)d_in[6];
    const float* Wihs = (const float*)d_in[7];
    const float* Whhs = (const float*)d_in[8];
    const float* bihs = (const float*)d_in[9];
    const float* bhhs = (const float*)d_in[10];
    const float* Wp   = (const float*)d_in[11];
    const float* bp   = (const float*)d_in[12];
    const float* Wc1  = (const float*)d_in[13];
    const float* bc1  = (const float*)d_in[14];
    const float* Wc2  = (const float*)d_in[15];
    const float* bc2  = (const float*)d_in[16];

    float* out_logits = (float*)d_out;
    float* out_h      = out_logits + (size_t)B_ * NC_;
    float* out_p      = out_h + (size_t)B_ * L_ * HL_;

    float* ggl; cudaGetSymbolAddress((void**)&ggl, g_gl);
    float* ggs; cudaGetSymbolAddress((void**)&ggs, g_gs);

    cudaFuncSetAttribute(k_rec, cudaFuncAttributeMaxDynamicSharedMemorySize, SMEM_REC);

    k_init<<<256, 256>>>(gu);
    {
        dim3 gl(4 * HL_ / 128, (B_ * L_) / 64);
        k_ingemm<4 * HL_><<<gl, 256>>>(x, emb, Wihl, bihl, bhhl, ggl);
        dim3 gs(4 * HS_ / 128, (B_ * L_) / 64);
        k_ingemm<4 * HS_><<<gs, 256>>>(x, emb, Wihs, bihs, bhhs, ggs);
    }
    k_pe<<<(B_ * L_ * 32 + 255) / 256, 256>>>(x, emb, Wp, bp, out_p);
    k_rec<<<144, 512, SMEM_REC>>>(Whhl, Whhs, Wp, out_h, out_p);
    k_cls<<<B_, 256>>>(Wc1, bc1, Wc2, bc2, out_logits);
    k_psoft<<<(B_ * L_ + 255) / 256, 256>>>(out_p);
}